// round 12
// baseline (speedup 1.0000x reference)
#include <cuda_runtime.h>

#define NODES 100000
#define NEDGE 1600000

__device__ unsigned g_deg [NODES];
__device__ float    g_dinv[NODES];
__device__ float4   g_xs  [NODES];   // dinv-scaled input features (layer-1 messages)
__device__ float4   g_acc1[NODES];   // layer-1 aggregation accumulator
__device__ float4   g_gs  [NODES];   // dinv-scaled layer-2 messages (after fused MLP)
__device__ float4   g_acc2[NODES];   // layer-2 aggregation accumulator

__device__ __forceinline__ void red_add_v4(float4* addr, float4 v) {
    asm volatile("red.global.add.v4.f32 [%0], {%1,%2,%3,%4};"
                 :: "l"(addr), "f"(v.x), "f"(v.y), "f"(v.z), "f"(v.w)
                 : "memory");
}

__device__ __forceinline__ void red_add_u32(unsigned* addr) {
    asm volatile("red.global.add.u32 [%0], 1;" :: "l"(addr) : "memory");
}

// deg[col[e]] += 1, 1 edge/thread.
__global__ void __launch_bounds__(256) k_deg_count(const int* __restrict__ col, int e) {
    int t = blockIdx.x * blockDim.x + threadIdx.x;
    if (t < e) red_add_u32(&g_deg[col[t]]);
    cudaTriggerProgrammaticLaunchCompletion();
}

// dinv = rsqrt(deg + 1 self-loop); xs = x * dinv; acc1 init = xs (self loop);
// deg cleared for the next replay (same-thread read-then-zero).
__global__ void k_node_pre(const float4* __restrict__ x, int n) {
    int i = blockIdx.x * blockDim.x + threadIdx.x;
    float4 v = make_float4(0.f, 0.f, 0.f, 0.f);
    if (i < n) v = x[i];                 // independent prologue load
    cudaGridDependencySynchronize();     // wait: all deg_count reds landed
    if (i < n) {
        float d = rsqrtf((float)(g_deg[i] + 1u));
        g_deg[i] = 0u;
        g_dinv[i] = d;
        v.x *= d; v.y *= d; v.z *= d; v.w *= d;
        g_xs[i]   = v;
        g_acc1[i] = v;
    }
    cudaTriggerProgrammaticLaunchCompletion();
}

// 1-edge scatter: dst[col[e]] += src[row[e]].
__global__ void __launch_bounds__(256) k_scatter(const int* __restrict__ row,
                                                 const int* __restrict__ col,
                                                 const float4* __restrict__ src,
                                                 float4* __restrict__ dst, int e) {
    int t = blockIdx.x * blockDim.x + threadIdx.x;
    int r = 0, c = 0;
    bool ok = t < e;
    if (ok) { r = __ldg(row + t); c = __ldg(col + t); }  // independent prologue
    cudaGridDependencySynchronize();     // wait: src fully written
    if (ok) red_add_v4(&dst[c], src[r]);
    cudaTriggerProgrammaticLaunchCompletion();
}

// Fused per-node MLP: 2 nodes/thread, TB=64 (782 blocks). Weight staging uses
// 3 vectorized LDG.128/thread (front-batch MLP_p1 9 -> 3, cutting cross-CTA
// L1tex-queue spread); g_dinv loaded pre-GDS (final by PDL transitivity:
// node_pre completed before scatter1 began).
__global__ void __launch_bounds__(64) k_mlp(const float* __restrict__ W1,
                                            const float* __restrict__ b1,
                                            const float* __restrict__ W2, int n) {
    __shared__ float sW1T[256];  // [j][i] : sW1T[j*4+i] = W1[i*64+j]
    __shared__ float sW2 [256];  // [j][c] row-major (native layout of W2)
    __shared__ float sB1 [64];
    int tid = threadIdx.x;

    // Batched vector staging loads (<=3 LDG.128 per thread, issued together).
    float4 w1v = ((const float4*)W1)[tid];                         // 64 float4
    float4 w2v = ((const float4*)W2)[tid];                         // 64 float4
    float4 bv  = make_float4(0.f, 0.f, 0.f, 0.f);
    if (tid < 16) bv = ((const float4*)b1)[tid];                   // 16 float4

    // Pre-GDS per-thread dinv load (one LDG.64).
    int i0   = (blockIdx.x * 64 + tid) * 2;
    bool has0 = (i0 < n);
    bool has1 = (i0 + 1 < n);
    float d0 = 0.f, d1 = 0.f;
    if (has1) {
        float2 dv = ((const float2*)g_dinv)[i0 >> 1];
        d0 = dv.x; d1 = dv.y;
    } else if (has0) {
        d0 = g_dinv[i0];
    }

    // Stage to smem (transpose W1 via scalar STS; W2/b1 vector STS).
    {
        int iW = tid >> 4;          // W1 row   (0..3)
        int jg = (tid & 15) * 4;    // W1 j-group base
        sW1T[(jg + 0) * 4 + iW] = w1v.x;
        sW1T[(jg + 1) * 4 + iW] = w1v.y;
        sW1T[(jg + 2) * 4 + iW] = w1v.z;
        sW1T[(jg + 3) * 4 + iW] = w1v.w;
        ((float4*)sW2)[tid] = w2v;
        if (tid < 16) ((float4*)sB1)[tid] = bv;
    }
    __syncthreads();
    cudaGridDependencySynchronize();     // wait: scatter1 reds landed

    const float4* w1t = (const float4*)sW1T;
    const float4* w2  = (const float4*)sW2;

    if (has0) {
        float4 a0 = g_acc1[i0];
        float4 a1 = has1 ? g_acc1[i0 + 1] : make_float4(0.f, 0.f, 0.f, 0.f);
        a0.x *= d0; a0.y *= d0; a0.z *= d0; a0.w *= d0;
        a1.x *= d1; a1.y *= d1; a1.z *= d1; a1.w *= d1;
        float4 g0 = make_float4(0.f, 0.f, 0.f, 0.f);
        float4 g1 = make_float4(0.f, 0.f, 0.f, 0.f);
        #pragma unroll
        for (int j = 0; j < 64; j++) {
            float4 w = w1t[j];
            float4 u = w2[j];
            float  b = sB1[j];
            float h0 = fmaf(a0.x, w.x, fmaf(a0.y, w.y, fmaf(a0.z, w.z, fmaf(a0.w, w.w, b))));
            float h1 = fmaf(a1.x, w.x, fmaf(a1.y, w.y, fmaf(a1.z, w.z, fmaf(a1.w, w.w, b))));
            h0 = fmaxf(h0, 0.0f);
            h1 = fmaxf(h1, 0.0f);
            g0.x = fmaf(h0, u.x, g0.x); g0.y = fmaf(h0, u.y, g0.y);
            g0.z = fmaf(h0, u.z, g0.z); g0.w = fmaf(h0, u.w, g0.w);
            g1.x = fmaf(h1, u.x, g1.x); g1.y = fmaf(h1, u.y, g1.y);
            g1.z = fmaf(h1, u.z, g1.z); g1.w = fmaf(h1, u.w, g1.w);
        }
        float4 s0 = make_float4(g0.x * d0, g0.y * d0, g0.z * d0, g0.w * d0);
        g_gs[i0]   = s0;  g_acc2[i0]   = s0;
        if (has1) {
            float4 s1 = make_float4(g1.x * d1, g1.y * d1, g1.z * d1, g1.w * d1);
            g_gs[i0 + 1] = s1;  g_acc2[i0 + 1] = s1;
        }
    }
    cudaTriggerProgrammaticLaunchCompletion();
}

// out = dinv * acc2 + b2
__global__ void k_final(const float* __restrict__ b2, float4* __restrict__ out, int n) {
    int i = blockIdx.x * blockDim.x + threadIdx.x;
    float bx = b2[0], by = b2[1], bz = b2[2], bw = b2[3];  // independent prologue
    cudaGridDependencySynchronize();     // wait: scatter2 reds landed
    if (i < n) {
        float d = g_dinv[i];
        float4 a = g_acc2[i];
        float4 o;
        o.x = fmaf(d, a.x, bx);
        o.y = fmaf(d, a.y, by);
        o.z = fmaf(d, a.z, bz);
        o.w = fmaf(d, a.w, bw);
        out[i] = o;
    }
    cudaTriggerProgrammaticLaunchCompletion();
}

template <typename... Args>
static inline void launch_pdl(void (*kern)(Args...), int grid, int block,
                              Args... args) {
    cudaLaunchConfig_t cfg = {};
    cfg.gridDim  = dim3(grid, 1, 1);
    cfg.blockDim = dim3(block, 1, 1);
    cfg.dynamicSmemBytes = 0;
    cfg.stream = 0;
    cudaLaunchAttribute attr[1];
    attr[0].id = cudaLaunchAttributeProgrammaticStreamSerialization;
    attr[0].val.programmaticStreamSerializationAllowed = 1;
    cfg.attrs = attr;
    cfg.numAttrs = 1;
    cudaLaunchKernelEx(&cfg, kern, args...);
}

extern "C" void kernel_launch(void* const* d_in, const int* in_sizes, int n_in,
                              void* d_out, int out_size) {
    const float* x  = (const float*)d_in[0];
    const int*   ei = (const int*)  d_in[1];
    const float* W1 = (const float*)d_in[2];
    const float* b1 = (const float*)d_in[3];
    const float* W2 = (const float*)d_in[4];
    const float* b2 = (const float*)d_in[5];

    int n = in_sizes[0] / 4;   // N nodes (S=4)
    int e = in_sizes[1] / 2;   // E edges
    const int* row = ei;
    const int* col = ei + e;

    void *p_xs, *p_acc1, *p_gs, *p_acc2;
    cudaGetSymbolAddress(&p_xs,   g_xs);
    cudaGetSymbolAddress(&p_acc1, g_acc1);
    cudaGetSymbolAddress(&p_gs,   g_gs);
    cudaGetSymbolAddress(&p_acc2, g_acc2);

    const int TB  = 256;
    const int TBM = 64;                          // mlp: 2-warp blocks
    int nb_n  = (n + TB - 1) / TB;
    int nb_e1 = (e + TB - 1) / TB;               // 1 edge/thread
    int nt_m  = (n + 1) / 2;                     // 2 nodes/thread (mlp)
    int nb_m  = (nt_m + TBM - 1) / TBM;          // 782 blocks

    launch_pdl(k_deg_count, nb_e1, TB, col, e);
    launch_pdl(k_node_pre,  nb_n,  TB, (const float4*)x, n);
    launch_pdl(k_scatter,   nb_e1, TB, row, col, (const float4*)p_xs, (float4*)p_acc1, e);
    launch_pdl(k_mlp,       nb_m,  TBM, W1, b1, W2, n);
    launch_pdl(k_scatter,   nb_e1, TB, row, col, (const float4*)p_gs, (float4*)p_acc2, e);
    launch_pdl(k_final,     nb_n,  TB, b2, (float4*)d_out, n);
}

// round 13
// speedup vs baseline: 1.6129x; 1.6129x over previous
#include <cuda_runtime.h>

#define NODES 100000
#define NEDGE 1600000

__device__ unsigned g_deg [NODES];
__device__ float    g_dinv[NODES];
__device__ float4   g_xs  [NODES];   // dinv-scaled input features (layer-1 messages)
__device__ float4   g_acc1[NODES];   // layer-1 aggregation accumulator
__device__ float4   g_gs  [NODES];   // dinv-scaled layer-2 messages (after fused MLP)
__device__ float4   g_acc2[NODES];   // layer-2 aggregation accumulator

__device__ __forceinline__ void red_add_v4(float4* addr, float4 v) {
    asm volatile("red.global.add.v4.f32 [%0], {%1,%2,%3,%4};"
                 :: "l"(addr), "f"(v.x), "f"(v.y), "f"(v.z), "f"(v.w)
                 : "memory");
}

__device__ __forceinline__ void red_add_u32(unsigned* addr) {
    asm volatile("red.global.add.u32 [%0], 1;" :: "l"(addr) : "memory");
}

// deg[col[e]] += 1, 1 edge/thread. Early trigger: successor may start its
// launch ramp immediately; its GDS still waits for our completion.
__global__ void __launch_bounds__(256) k_deg_count(const int* __restrict__ col, int e) {
    cudaTriggerProgrammaticLaunchCompletion();
    int t = blockIdx.x * blockDim.x + threadIdx.x;
    if (t < e) red_add_u32(&g_deg[col[t]]);
}

// dinv = rsqrt(deg + 1 self-loop); xs = x * dinv; acc1 init = xs (self loop);
// deg cleared for the next replay (same-thread read-then-zero).
__global__ void k_node_pre(const float4* __restrict__ x, int n) {
    int i = blockIdx.x * blockDim.x + threadIdx.x;
    float4 v = make_float4(0.f, 0.f, 0.f, 0.f);
    if (i < n) v = x[i];                 // independent prologue load
    cudaGridDependencySynchronize();     // wait: all deg_count reds landed
    cudaTriggerProgrammaticLaunchCompletion();
    if (i < n) {
        float d = rsqrtf((float)(g_deg[i] + 1u));
        g_deg[i] = 0u;
        g_dinv[i] = d;
        v.x *= d; v.y *= d; v.z *= d; v.w *= d;
        g_xs[i]   = v;
        g_acc1[i] = v;
    }
}

// 1-edge scatter: dst[col[e]] += src[row[e]].
__global__ void __launch_bounds__(256) k_scatter(const int* __restrict__ row,
                                                 const int* __restrict__ col,
                                                 const float4* __restrict__ src,
                                                 float4* __restrict__ dst, int e) {
    int t = blockIdx.x * blockDim.x + threadIdx.x;
    int r = 0, c = 0;
    bool ok = t < e;
    if (ok) { r = __ldg(row + t); c = __ldg(col + t); }  // independent prologue
    cudaGridDependencySynchronize();     // wait: src fully written
    cudaTriggerProgrammaticLaunchCompletion();
    if (ok) red_add_v4(&dst[c], src[r]);
}

// Fused per-node MLP: 2 nodes/thread, TB=64 (782 balanced 2-warp blocks).
// Weight staging to smem is independent of scatter1; GDS before reading acc1.
__global__ void __launch_bounds__(64) k_mlp(const float* __restrict__ W1,
                                            const float* __restrict__ b1,
                                            const float* __restrict__ W2, int n) {
    __shared__ float sW1T[256];  // [j][i] : sW1T[j*4+i] = W1[i*64+j]
    __shared__ float sW2 [256];  // [j][c] row-major (native layout of W2)
    __shared__ float sB1 [64];
    int tid = threadIdx.x;
    #pragma unroll
    for (int k = tid; k < 256; k += 64) {
        sW1T[(k & 63) * 4 + (k >> 6)] = W1[k];  // transpose on load
        sW2[k] = W2[k];
    }
    sB1[tid] = b1[tid];
    __syncthreads();
    cudaGridDependencySynchronize();     // wait: scatter1 reds landed
    cudaTriggerProgrammaticLaunchCompletion();

    const float4* w1t = (const float4*)sW1T;
    const float4* w2  = (const float4*)sW2;

    int i0 = (blockIdx.x * blockDim.x + tid) * 2;
    if (i0 + 1 < n) {
        float d0 = g_dinv[i0],  d1 = g_dinv[i0 + 1];
        float4 a0 = g_acc1[i0], a1 = g_acc1[i0 + 1];
        a0.x *= d0; a0.y *= d0; a0.z *= d0; a0.w *= d0;
        a1.x *= d1; a1.y *= d1; a1.z *= d1; a1.w *= d1;
        float4 g0 = make_float4(0.f, 0.f, 0.f, 0.f);
        float4 g1 = make_float4(0.f, 0.f, 0.f, 0.f);
        #pragma unroll
        for (int j = 0; j < 64; j++) {
            float4 w = w1t[j];
            float4 u = w2[j];
            float  b = sB1[j];
            float h0 = fmaf(a0.x, w.x, fmaf(a0.y, w.y, fmaf(a0.z, w.z, fmaf(a0.w, w.w, b))));
            float h1 = fmaf(a1.x, w.x, fmaf(a1.y, w.y, fmaf(a1.z, w.z, fmaf(a1.w, w.w, b))));
            h0 = fmaxf(h0, 0.0f);
            h1 = fmaxf(h1, 0.0f);
            g0.x = fmaf(h0, u.x, g0.x); g0.y = fmaf(h0, u.y, g0.y);
            g0.z = fmaf(h0, u.z, g0.z); g0.w = fmaf(h0, u.w, g0.w);
            g1.x = fmaf(h1, u.x, g1.x); g1.y = fmaf(h1, u.y, g1.y);
            g1.z = fmaf(h1, u.z, g1.z); g1.w = fmaf(h1, u.w, g1.w);
        }
        float4 s0 = make_float4(g0.x * d0, g0.y * d0, g0.z * d0, g0.w * d0);
        float4 s1 = make_float4(g1.x * d1, g1.y * d1, g1.z * d1, g1.w * d1);
        g_gs[i0]     = s0;  g_acc2[i0]     = s0;
        g_gs[i0 + 1] = s1;  g_acc2[i0 + 1] = s1;
    } else if (i0 < n) {
        float d = g_dinv[i0];
        float4 a = g_acc1[i0];
        a.x *= d; a.y *= d; a.z *= d; a.w *= d;
        float4 g = make_float4(0.f, 0.f, 0.f, 0.f);
        #pragma unroll
        for (int j = 0; j < 64; j++) {
            float4 w = w1t[j];
            float4 u = w2[j];
            float h = fmaf(a.x, w.x, fmaf(a.y, w.y, fmaf(a.z, w.z, fmaf(a.w, w.w, sB1[j]))));
            h = fmaxf(h, 0.0f);
            g.x = fmaf(h, u.x, g.x); g.y = fmaf(h, u.y, g.y);
            g.z = fmaf(h, u.z, g.z); g.w = fmaf(h, u.w, g.w);
        }
        float4 s = make_float4(g.x * d, g.y * d, g.z * d, g.w * d);
        g_gs[i0] = s;  g_acc2[i0] = s;
    }
}

// out = dinv * acc2 + b2
__global__ void k_final(const float* __restrict__ b2, float4* __restrict__ out, int n) {
    int i = blockIdx.x * blockDim.x + threadIdx.x;
    float bx = b2[0], by = b2[1], bz = b2[2], bw = b2[3];  // independent prologue
    cudaGridDependencySynchronize();     // wait: scatter2 reds landed
    cudaTriggerProgrammaticLaunchCompletion();
    if (i < n) {
        float d = g_dinv[i];
        float4 a = g_acc2[i];
        float4 o;
        o.x = fmaf(d, a.x, bx);
        o.y = fmaf(d, a.y, by);
        o.z = fmaf(d, a.z, bz);
        o.w = fmaf(d, a.w, bw);
        out[i] = o;
    }
}

template <typename... Args>
static inline void launch_pdl(void (*kern)(Args...), int grid, int block,
                              Args... args) {
    cudaLaunchConfig_t cfg = {};
    cfg.gridDim  = dim3(grid, 1, 1);
    cfg.blockDim = dim3(block, 1, 1);
    cfg.dynamicSmemBytes = 0;
    cfg.stream = 0;
    cudaLaunchAttribute attr[1];
    attr[0].id = cudaLaunchAttributeProgrammaticStreamSerialization;
    attr[0].val.programmaticStreamSerializationAllowed = 1;
    cfg.attrs = attr;
    cfg.numAttrs = 1;
    cudaLaunchKernelEx(&cfg, kern, args...);
}

extern "C" void kernel_launch(void* const* d_in, const int* in_sizes, int n_in,
                              void* d_out, int out_size) {
    const float* x  = (const float*)d_in[0];
    const int*   ei = (const int*)  d_in[1];
    const float* W1 = (const float*)d_in[2];
    const float* b1 = (const float*)d_in[3];
    const float* W2 = (const float*)d_in[4];
    const float* b2 = (const float*)d_in[5];

    int n = in_sizes[0] / 4;   // N nodes (S=4)
    int e = in_sizes[1] / 2;   // E edges
    const int* row = ei;
    const int* col = ei + e;

    void *p_xs, *p_acc1, *p_gs, *p_acc2;
    cudaGetSymbolAddress(&p_xs,   g_xs);
    cudaGetSymbolAddress(&p_acc1, g_acc1);
    cudaGetSymbolAddress(&p_gs,   g_gs);
    cudaGetSymbolAddress(&p_acc2, g_acc2);

    const int TB  = 256;
    const int TBM = 64;                          // mlp: 2-warp blocks, balanced waves
    int nb_n  = (n + TB - 1) / TB;
    int nb_e1 = (e + TB - 1) / TB;               // 1 edge/thread
    int nt_m  = (n + 1) / 2;                     // 2 nodes/thread (mlp)
    int nb_m  = (nt_m + TBM - 1) / TBM;          // 782 blocks

    launch_pdl(k_deg_count, nb_e1, TB, col, e);
    launch_pdl(k_node_pre,  nb_n,  TB, (const float4*)x, n);
    launch_pdl(k_scatter,   nb_e1, TB, row, col, (const float4*)p_xs, (float4*)p_acc1, e);
    launch_pdl(k_mlp,       nb_m,  TBM, W1, b1, W2, n);
    launch_pdl(k_scatter,   nb_e1, TB, row, col, (const float4*)p_gs, (float4*)p_acc2, e);
    launch_pdl(k_final,     nb_n,  TB, b2, (float4*)d_out, n);
}